// round 17
// baseline (speedup 1.0000x reference)
#include <cuda_runtime.h>
#include <cuda_fp16.h>
#include <cuda_bf16.h>
#include <cuda_fp8.h>
#include <math.h>
#include <stdint.h>

// ---------------------------------------------------------------------------
// Problem constants (fixed by the reference)
// ---------------------------------------------------------------------------
#define NA        4096
#define ED        256      // EMBED_DIMS
#define NG        8        // NUM_GROUPS
#define GD        32       // GROUP_DIMS
#define NL        4        // NUM_LEVELS
#define NC        6        // NUM_CAMS
#define NPT       13       // NUM_PTS (7 fixed + 6 learnable)
#define NSAMP     312      // NC*NL*NPT
#define NSAMPP    313      // padded (bank destagger)
#define NWTS      2496     // NSAMP*NG
#define MAXCOR    1280     // >= NSAMP*4

// level dims
__constant__ int   c_LW[4] = {176, 88, 44, 22};
__constant__ int   c_LH[4] = {64, 32, 16, 8};
__constant__ unsigned c_LB[4] = {0u, 17301504u, 21626880u, 22708224u};  // byte offsets (1B/elem)
__constant__ int   c_HW[4] = {11264, 2816, 704, 176};
__constant__ int   c_tileBase[5] = {0, 352, 440, 462, 468};  // cumulative 32-wide hw tiles

__constant__ float c_fix[21] = {
    0.f,0.f,0.f,  0.45f,0.f,0.f,  -0.45f,0.f,0.f,
    0.f,0.45f,0.f, 0.f,-0.45f,0.f, 0.f,0.f,0.45f, 0.f,0.f,-0.45f
};

// ---------------------------------------------------------------------------
// Scratch (static __device__ — device-code references ONLY; host-side address
// of a __device__ symbol is the host shadow and silently "works" via ATS).
// ---------------------------------------------------------------------------
__device__ __align__(16) unsigned char g_f8[22978560]; // 4 levels, NHWC, fp8 e4m3
__device__ float  g_logits[NA * NWTS];      // weight logits (softmaxed in agg)
__device__ float  g_p2d[NA * NPT * NC * 2]; // projected points
__device__ float  g_feats[NA * ED];         // aggregated features

// ---------------------------------------------------------------------------
// 1) Fused CHW -> HWC transpose + fp32->fp8(e4m3), ALL levels, 1 launch.
//    Loads: one float4 (LDG.128) per thread; stores: uchar4 per thread.
// ---------------------------------------------------------------------------
__global__ void transpose_all(const float* __restrict__ f0, const float* __restrict__ f1,
                              const float* __restrict__ f2, const float* __restrict__ f3) {
    __shared__ float tile[32][33];
    int bx = blockIdx.x;
    int lvl = 0;
#pragma unroll
    for (int l = 1; l < 4; l++) if (bx >= c_tileBase[l]) lvl = l;
    const float* src = (lvl == 0) ? f0 : (lvl == 1) ? f1 : (lvl == 2) ? f2 : f3;
    int HW = c_HW[lvl];
    unsigned dst_base = c_LB[lvl];

    int cam = blockIdx.z;
    int hw0 = (bx - c_tileBase[lvl]) * 32;
    int c0  = blockIdx.y * 32;
    const float* s = src + (size_t)cam * ED * HW;
    unsigned char* d = g_f8 + dst_base + (size_t)cam * HW * ED;
    int tid = threadIdx.y * 32 + threadIdx.x;

    // load phase: thread -> (channel row c, 4-wide hw quad); 1 LDG.128 + 4 STS
    {
        int c   = tid >> 3;           // 0..31
        int hwq = tid & 7;            // 0..7
        int hw  = hw0 + hwq * 4;
        float4 v = make_float4(0.f, 0.f, 0.f, 0.f);
        if (hw < HW)                  // HW%4==0 && hw%4==0 => all 4 in range
            v = *reinterpret_cast<const float4*>(s + (size_t)(c0 + c) * HW + hw);
        tile[c][hwq * 4 + 0] = v.x;
        tile[c][hwq * 4 + 1] = v.y;
        tile[c][hwq * 4 + 2] = v.z;
        tile[c][hwq * 4 + 3] = v.w;
    }
    __syncthreads();
    // store phase: thread -> (hw row, 4-channel group); conflict-free smem reads
    {
        int hwl = tid >> 3;       // 0..31
        int cg  = tid & 7;        // 0..7 (4 channels each)
        int hw  = hw0 + hwl;
        if (hw < HW) {
            uchar4 v;
            v.x = (unsigned char)__nv_cvt_float_to_fp8(tile[cg*4+0][hwl], __NV_SATFINITE, __NV_E4M3);
            v.y = (unsigned char)__nv_cvt_float_to_fp8(tile[cg*4+1][hwl], __NV_SATFINITE, __NV_E4M3);
            v.z = (unsigned char)__nv_cvt_float_to_fp8(tile[cg*4+2][hwl], __NV_SATFINITE, __NV_E4M3);
            v.w = (unsigned char)__nv_cvt_float_to_fp8(tile[cg*4+3][hwl], __NV_SATFINITE, __NV_E4M3);
            *reinterpret_cast<uchar4*>(d + (size_t)hw * ED + c0 + cg * 4) = v;
        }
    }
}

// ---------------------------------------------------------------------------
// 2) Per-anchor setup: learnable points (parallel GEMV), rotation, projection.
//    256 threads; GEMV split over 144 threads (18 cols x 8 k-slices).
// ---------------------------------------------------------------------------
__global__ void __launch_bounds__(256) setup_kernel(
    const float* __restrict__ inst, const float* __restrict__ anchor,
    const float* __restrict__ proj, const float* __restrict__ wh,
    const float* __restrict__ Wl, const float* __restrict__ bl)
{
    int a = blockIdx.x;
    int tid = threadIdx.x;
    __shared__ float sif[ED];
    __shared__ float red[18 * 8];
    __shared__ float sscale[NPT * 3];
    __shared__ float skp[NPT * 3];
    __shared__ float sR[9];
    __shared__ float sts[6];

    sif[tid] = inst[(size_t)a * ED + tid];
    if (tid < 21) sscale[tid] = c_fix[tid];
    __syncthreads();

    // learnable GEMV partials: col = tid/8, k-slice = tid%8 (32 k each)
    if (tid < 144) {
        int col = tid >> 3, sl = tid & 7;
        float acc = 0.f;
        int kb = sl * 32;
#pragma unroll 8
        for (int k = 0; k < 32; k++) acc = fmaf(sif[kb + k], Wl[(kb + k) * 18 + col], acc);
        red[col * 8 + sl] = acc;
    }
    if (tid == 192) {
        const float* an = anchor + (size_t)a * 11;
        float t0 = an[0], t1 = an[1], t2 = an[2];
        float s0 = an[3], s1 = an[4], s2 = an[5];
        float qw = an[6], qx = an[7], qy = an[8], qz = an[9];
        float inv = rsqrtf(qw*qw + qx*qx + qy*qy + qz*qz);
        qw *= inv; qx *= inv; qy *= inv; qz *= inv;
        float R00 = 1.f - 2.f*(qy*qy + qz*qz), R01 = 2.f*(qx*qy - qw*qz), R02 = 2.f*(qx*qz + qw*qy);
        float R10 = 2.f*(qx*qy + qw*qz), R11 = 1.f - 2.f*(qx*qx + qz*qz), R12 = 2.f*(qy*qz - qw*qx);
        float R20 = 2.f*(qx*qz - qw*qy), R21 = 2.f*(qy*qz + qw*qx), R22 = 1.f - 2.f*(qx*qx + qy*qy);
        sR[0] = R00; sR[1] = R10; sR[2] = R20;
        sR[3] = R01; sR[4] = R11; sR[5] = R21;
        sR[6] = R02; sR[7] = R12; sR[8] = R22;
        sts[0] = t0; sts[1] = t1; sts[2] = t2;
        sts[3] = s0; sts[4] = s1; sts[5] = s2;
    }
    __syncthreads();

    if (tid < 18) {
        float acc = bl[tid];
#pragma unroll
        for (int sl = 0; sl < 8; sl++) acc += red[tid * 8 + sl];
        acc = fminf(fmaxf(acc, -9.21f), 9.21f);
        float sg = 1.f / (1.f + expf(-acc));
        sscale[21 + tid] = sg - 0.5f;
    }
    __syncthreads();

    if (tid < NPT) {
        float v0 = sscale[tid*3+0] * sts[3];
        float v1 = sscale[tid*3+1] * sts[4];
        float v2 = sscale[tid*3+2] * sts[5];
        skp[tid*3+0] = sR[0]*v0 + sR[1]*v1 + sR[2]*v2 + sts[0];
        skp[tid*3+1] = sR[3]*v0 + sR[4]*v1 + sR[5]*v2 + sts[1];
        skp[tid*3+2] = sR[6]*v0 + sR[7]*v1 + sR[8]*v2 + sts[2];
    }
    __syncthreads();
    if (tid < NPT * NC) {
        int pt = tid / NC, cam = tid % NC;
        float x = skp[pt*3+0], y = skp[pt*3+1], z = skp[pt*3+2];
        const float* P = proj + cam * 16;
        float px = P[0]*x + P[1]*y + P[2]*z  + P[3];
        float py = P[4]*x + P[5]*y + P[6]*z  + P[7];
        float pz = P[8]*x + P[9]*y + P[10]*z + P[11];
        pz = fmaxf(pz, 1e-5f);
        float u = (px / pz) / wh[cam*2+0];
        float v = (py / pz) / wh[cam*2+1];
        u = fminf(fmaxf(u, 0.f), 0.9999f);
        v = fminf(fmaxf(v, 0.f), 0.9999f);
        g_p2d[((size_t)a * (NPT*NC) + tid) * 2 + 0] = u;
        g_p2d[((size_t)a * (NPT*NC) + tid) * 2 + 1] = v;
    }
}

// ---------------------------------------------------------------------------
// 3) Logits GEMM, bf16 tensor cores, BM=128 BN=96 (R16-proven).
// ---------------------------------------------------------------------------
__global__ void __launch_bounds__(256) gemm_logits96(
    const float* __restrict__ A, const float* __restrict__ Bm,
    const float* __restrict__ bias)
{
    float* C = g_logits;
    const int N = NWTS, K = ED;
    __shared__ __nv_bfloat16 As[128][72];
    __shared__ __nv_bfloat16 Bst[96][72];

    int tid = threadIdx.x;
    int lane = tid & 31, w = tid >> 5;
    int wm = w & 3, wn = w >> 2;
    int m0 = blockIdx.y * 128, n0 = blockIdx.x * 96;
    int g = lane >> 2, t = lane & 3;

    float d[2][6][4];
#pragma unroll
    for (int mt = 0; mt < 2; mt++)
#pragma unroll
        for (int nt = 0; nt < 6; nt++)
#pragma unroll
            for (int r = 0; r < 4; r++) d[mt][nt][r] = 0.f;

    for (int k0 = 0; k0 < K; k0 += 64) {
#pragma unroll
        for (int i = 0; i < 32; i++) {
            int e = i * 256 + tid;
            int row = e >> 6, kk = e & 63;
            As[row][kk] = __float2bfloat16(A[(size_t)(m0 + row) * K + k0 + kk]);
        }
#pragma unroll
        for (int i = 0; i < 24; i++) {
            int e = i * 256 + tid;
            int kk = e / 96, n = e % 96;
            Bst[n][kk] = __float2bfloat16(Bm[(size_t)(k0 + kk) * N + n0 + n]);
        }
        __syncthreads();
#pragma unroll
        for (int ks = 0; ks < 4; ks++) {
            int kb = ks * 16;
            unsigned a[2][4], b[6][2];
#pragma unroll
            for (int mt = 0; mt < 2; mt++) {
                int rb = wm * 32 + mt * 16;
                a[mt][0] = *(const unsigned*)&As[rb + g][kb + 2 * t];
                a[mt][1] = *(const unsigned*)&As[rb + g + 8][kb + 2 * t];
                a[mt][2] = *(const unsigned*)&As[rb + g][kb + 2 * t + 8];
                a[mt][3] = *(const unsigned*)&As[rb + g + 8][kb + 2 * t + 8];
            }
#pragma unroll
            for (int nt = 0; nt < 6; nt++) {
                int cb = wn * 48 + nt * 8;
                b[nt][0] = *(const unsigned*)&Bst[cb + g][kb + 2 * t];
                b[nt][1] = *(const unsigned*)&Bst[cb + g][kb + 2 * t + 8];
            }
#pragma unroll
            for (int mt = 0; mt < 2; mt++)
#pragma unroll
                for (int nt = 0; nt < 6; nt++)
                    asm volatile(
                        "mma.sync.aligned.m16n8k16.row.col.f32.bf16.bf16.f32 "
                        "{%0,%1,%2,%3}, {%4,%5,%6,%7}, {%8,%9}, {%0,%1,%2,%3};"
                        : "+f"(d[mt][nt][0]), "+f"(d[mt][nt][1]),
                          "+f"(d[mt][nt][2]), "+f"(d[mt][nt][3])
                        : "r"(a[mt][0]), "r"(a[mt][1]), "r"(a[mt][2]), "r"(a[mt][3]),
                          "r"(b[nt][0]), "r"(b[nt][1]));
        }
        __syncthreads();
    }
#pragma unroll
    for (int mt = 0; mt < 2; mt++) {
        int rb = m0 + wm * 32 + mt * 16;
#pragma unroll
        for (int nt = 0; nt < 6; nt++) {
            int n = n0 + wn * 48 + nt * 8 + 2 * t;
            float b0 = bias[n], b1 = bias[n + 1];
            C[(size_t)(rb + g) * N + n]         = d[mt][nt][0] + b0;
            C[(size_t)(rb + g) * N + n + 1]     = d[mt][nt][1] + b1;
            C[(size_t)(rb + g + 8) * N + n]     = d[mt][nt][2] + b0;
            C[(size_t)(rb + g + 8) * N + n + 1] = d[mt][nt][3] + b1;
        }
    }
}

// ---------------------------------------------------------------------------
// 5) Out GEMM (bf16 tensor cores): d_out = g_feats @ Wo + bo + inst
// ---------------------------------------------------------------------------
__global__ void __launch_bounds__(256) gemm_bf16_out(
    const float* __restrict__ Bm, const float* __restrict__ bias,
    const float* __restrict__ res, float* __restrict__ C)
{
    const float* A = g_feats;
    const int N = ED, K = ED;
    __shared__ __nv_bfloat16 As[128][72];
    __shared__ __nv_bfloat16 Bst[64][72];

    int tid = threadIdx.x;
    int lane = tid & 31, w = tid >> 5;
    int wm = w & 3, wn = w >> 2;
    int m0 = blockIdx.y * 128, n0 = blockIdx.x * 64;
    int g = lane >> 2, t = lane & 3;

    float d[2][4][4];
#pragma unroll
    for (int mt = 0; mt < 2; mt++)
#pragma unroll
        for (int nt = 0; nt < 4; nt++)
#pragma unroll
            for (int r = 0; r < 4; r++) d[mt][nt][r] = 0.f;

    for (int k0 = 0; k0 < K; k0 += 64) {
#pragma unroll
        for (int i = 0; i < 32; i++) {
            int e = i * 256 + tid;
            int row = e >> 6, kk = e & 63;
            As[row][kk] = __float2bfloat16(A[(size_t)(m0 + row) * K + k0 + kk]);
        }
#pragma unroll
        for (int i = 0; i < 16; i++) {
            int e = i * 256 + tid;
            int kk = e >> 6, n = e & 63;
            Bst[n][kk] = __float2bfloat16(Bm[(size_t)(k0 + kk) * N + n0 + n]);
        }
        __syncthreads();
#pragma unroll
        for (int ks = 0; ks < 4; ks++) {
            int kb = ks * 16;
            unsigned a[2][4], b[4][2];
#pragma unroll
            for (int mt = 0; mt < 2; mt++) {
                int rb = wm * 32 + mt * 16;
                a[mt][0] = *(const unsigned*)&As[rb + g][kb + 2 * t];
                a[mt][1] = *(const unsigned*)&As[rb + g + 8][kb + 2 * t];
                a[mt][2] = *(const unsigned*)&As[rb + g][kb + 2 * t + 8];
                a[mt][3] = *(const unsigned*)&As[rb + g + 8][kb + 2 * t + 8];
            }
#pragma unroll
            for (int nt = 0; nt < 4; nt++) {
                int cb = wn * 32 + nt * 8;
                b[nt][0] = *(const unsigned*)&Bst[cb + g][kb + 2 * t];
                b[nt][1] = *(const unsigned*)&Bst[cb + g][kb + 2 * t + 8];
            }
#pragma unroll
            for (int mt = 0; mt < 2; mt++)
#pragma unroll
                for (int nt = 0; nt < 4; nt++)
                    asm volatile(
                        "mma.sync.aligned.m16n8k16.row.col.f32.bf16.bf16.f32 "
                        "{%0,%1,%2,%3}, {%4,%5,%6,%7}, {%8,%9}, {%0,%1,%2,%3};"
                        : "+f"(d[mt][nt][0]), "+f"(d[mt][nt][1]),
                          "+f"(d[mt][nt][2]), "+f"(d[mt][nt][3])
                        : "r"(a[mt][0]), "r"(a[mt][1]), "r"(a[mt][2]), "r"(a[mt][3]),
                          "r"(b[nt][0]), "r"(b[nt][1]));
        }
        __syncthreads();
    }
#pragma unroll
    for (int mt = 0; mt < 2; mt++) {
        int rb = m0 + wm * 32 + mt * 16;
#pragma unroll
        for (int nt = 0; nt < 4; nt++) {
            int n = n0 + wn * 32 + nt * 8 + 2 * t;
            float b0 = bias[n], b1 = bias[n + 1];
            float v00 = d[mt][nt][0] + b0 + res[(size_t)(rb + g) * N + n];
            float v01 = d[mt][nt][1] + b1 + res[(size_t)(rb + g) * N + n + 1];
            float v10 = d[mt][nt][2] + b0 + res[(size_t)(rb + g + 8) * N + n];
            float v11 = d[mt][nt][3] + b1 + res[(size_t)(rb + g + 8) * N + n + 1];
            C[(size_t)(rb + g) * N + n]         = v00;
            C[(size_t)(rb + g) * N + n + 1]     = v01;
            C[(size_t)(rb + g + 8) * N + n]     = v10;
            C[(size_t)(rb + g + 8) * N + n + 1] = v11;
        }
    }
}

// ---------------------------------------------------------------------------
// per-sample bilinear corner metadata (shared by count & fill passes)
// ---------------------------------------------------------------------------
struct Corners {
    unsigned o[4];   // uint2-unit offsets (8 fp8 bytes per unit)
    float    w[4];   // bilinear weights (0 if invalid)
};

__device__ __forceinline__ Corners corner_meta(float2 p, int s) {
    int cam = s / (NL * NPT);
    int rr  = s % (NL * NPT);
    int lvl = rr / NPT;
    Corners r;
    int W = c_LW[lvl], H = c_LH[lvl];
    float x = p.x * (float)W - 0.5f;
    float y = p.y * (float)H - 0.5f;
    float xf = floorf(x), yf = floorf(y);
    float wx = x - xf, wy = y - yf;
    int x0 = (int)xf, y0 = (int)yf;
    int x1 = x0 + 1, y1 = y0 + 1;
    bool vx0 = (x0 >= 0) & (x0 < W);
    bool vx1 = (x1 >= 0) & (x1 < W);
    bool vy0 = (y0 >= 0) & (y0 < H);
    bool vy1 = (y1 >= 0) & (y1 < H);
    r.w[0] = (vx0 && vy0) ? (1.f - wx) * (1.f - wy) : 0.f;
    r.w[1] = (vx1 && vy0) ? wx * (1.f - wy) : 0.f;
    r.w[2] = (vx0 && vy1) ? (1.f - wx) * wy : 0.f;
    r.w[3] = (vx1 && vy1) ? wx * wy : 0.f;
    int x0c = min(max(x0, 0), W - 1), x1c = min(max(x1, 0), W - 1);
    int y0c = min(max(y0, 0), H - 1), y1c = min(max(y1, 0), H - 1);
    unsigned lb = c_LB[lvl];
    unsigned rowb = (unsigned)(cam * H);
    r.o[0] = (lb + ((rowb + (unsigned)y0c) * (unsigned)W + (unsigned)x0c) * 256u) >> 3;
    r.o[1] = (lb + ((rowb + (unsigned)y0c) * (unsigned)W + (unsigned)x1c) * 256u) >> 3;
    r.o[2] = (lb + ((rowb + (unsigned)y1c) * (unsigned)W + (unsigned)x0c) * 256u) >> 3;
    r.o[3] = (lb + ((rowb + (unsigned)y1c) * (unsigned)W + (unsigned)x1c) * 256u) >> 3;
    return r;
}

// ---------------------------------------------------------------------------
// 4) Fused softmax + compacted bilinear aggregation (fp8, half2 MAC).
//    Softmaxed weights re-stored as HALF in a table aliased onto spart
//    (dead until post-loop) -> hot-loop weight math is hmul+h2h2.
// ---------------------------------------------------------------------------
__global__ void __launch_bounds__(256) agg_kernel() {
    int a = blockIdx.x;
    int tid = threadIdx.x;
    int lane = tid & 31, warp = tid >> 5;

    __shared__ float  sw[NG * NSAMPP];            // softmaxed weights (float), [g][s]
    __shared__ float2 sp2[NPT * NC];
    __shared__ __align__(8) uint2 flist[MAXCOR];  // (off8, s<<16 | w_half)
    __shared__ int scnt[320];
    __shared__ int sbase[NSAMP];
    __shared__ int sT;
    __shared__ __align__(16) float spart[8 * ED]; // post-loop partials; aliases swh during loop

    __half* swh = (__half*)spart;                 // half weight table [g][s], 5008 B

    const float* lrow = g_logits + (size_t)a * NWTS;
    for (int i = tid; i < NWTS; i += 256) {
        int s = i >> 3, g = i & 7;
        sw[g * NSAMPP + s] = lrow[i];
    }
    if (tid < NPT * NC) sp2[tid] = ((const float2*)g_p2d)[(size_t)a * (NPT*NC) + tid];
    if (tid >= NSAMP && tid < 320) scnt[tid] = 0;
    __syncthreads();

    // per-group softmax over 312 entries (warp g handles group g; conflict-free)
    {
        float* swg = sw + warp * NSAMPP;
        float m = -1e30f;
        for (int i = lane; i < NSAMP; i += 32) m = fmaxf(m, swg[i]);
#pragma unroll
        for (int o = 16; o > 0; o >>= 1) m = fmaxf(m, __shfl_xor_sync(0xffffffffu, m, o));
        float ssum = 0.f;
        for (int i = lane; i < NSAMP; i += 32) {
            float e = __expf(swg[i] - m);
            swg[i] = e;
            ssum += e;
        }
#pragma unroll
        for (int o = 16; o > 0; o >>= 1) ssum += __shfl_xor_sync(0xffffffffu, ssum, o);
        float inv = 1.f / ssum;
        for (int i = lane; i < NSAMP; i += 32) swg[i] *= inv;
    }
    __syncthreads();

    // convert weight table to half (into spart alias)
    for (int i = tid; i < NWTS; i += 256) {
        int s = i >> 3, g = i & 7;
        swh[g * NSAMPP + s] = __float2half(sw[g * NSAMPP + s]);
    }

    // pass 1: per-sample valid-corner counts
    for (int s = tid; s < NSAMP; s += 256) {
        int pt = (s % (NL * NPT)) % NPT, cam = s / (NL * NPT);
        Corners cr = corner_meta(sp2[pt * NC + cam], s);
        scnt[s] = (cr.w[0] != 0.f) + (cr.w[1] != 0.f) + (cr.w[2] != 0.f) + (cr.w[3] != 0.f);
    }
    __syncthreads();

    // deterministic exclusive scan over 312 counts
    if (tid < 32) {
        int l = tid;
        int tot = 0;
#pragma unroll
        for (int k = 0; k < 10; k++) {
            int s = l * 10 + k;
            tot += (s < NSAMP) ? scnt[s] : 0;
        }
        int inc = tot;
#pragma unroll
        for (int o = 1; o < 32; o <<= 1) {
            int v = __shfl_up_sync(0xffffffffu, inc, o);
            if (l >= o) inc += v;
        }
        int run = inc - tot;
#pragma unroll
        for (int k = 0; k < 10; k++) {
            int s = l * 10 + k;
            if (s < NSAMP) { sbase[s] = run; run += scnt[s]; }
        }
        if (l == 31) sT = run;
    }
    __syncthreads();

    // pass 2: fill compacted corner list (weight stored as half)
    for (int s = tid; s < NSAMP; s += 256) {
        int pt = (s % (NL * NPT)) % NPT, cam = s / (NL * NPT);
        Corners cr = corner_meta(sp2[pt * NC + cam], s);
        int b = sbase[s];
        unsigned shi = ((unsigned)s) << 16;
#pragma unroll
        for (int k = 0; k < 4; k++) {
            if (cr.w[k] != 0.f) {
                unsigned wbits = (unsigned)__half_as_ushort(__float2half_rn(cr.w[k]));
                flist[b] = make_uint2(cr.o[k], shi | wbits);
                b++;
            }
        }
    }
    __syncthreads();

    const int T = sT;
    int g = lane >> 2;                    // group of this 8-channel slab
    const __half* swgh = swh + g * NSAMPP;
    __half2 hz = __float2half2_rn(0.f);
    __half2 h0 = hz, h1 = hz, h2a = hz, h3 = hz;
    const uint2* __restrict__ F8 = (const uint2*)g_f8;
#pragma unroll 4
    for (int j = warp; j < T; j += 8) {
        uint2 e = flist[j];                                   // broadcast LDS.64
        __half w = __hmul(swgh[e.y >> 16],
                          __ushort_as_half((unsigned short)(e.y & 0xffffu)));
        __half2 wh = __half2half2(w);
        uint2 u = __ldg(F8 + e.x + lane);
        __half2_raw r0 = __nv_cvt_fp8x2_to_halfraw2((__nv_fp8x2_storage_t)(u.x & 0xffffu), __NV_E4M3);
        __half2_raw r1 = __nv_cvt_fp8x2_to_halfraw2((__nv_fp8x2_storage_t)(u.x >> 16), __NV_E4M3);
        __half2_raw r2 = __nv_cvt_fp8x2_to_halfraw2((__nv_fp8x2_storage_t)(u.y & 0xffffu), __NV_E4M3);
        __half2_raw r3 = __nv_cvt_fp8x2_to_halfraw2((__nv_fp8x2_storage_t)(u.y >> 16), __NV_E4M3);
        h0  = __hfma2(wh, *reinterpret_cast<__half2*>(&r0), h0);
        h1  = __hfma2(wh, *reinterpret_cast<__half2*>(&r1), h1);
        h2a = __hfma2(wh, *reinterpret_cast<__half2*>(&r2), h2a);
        h3  = __hfma2(wh, *reinterpret_cast<__half2*>(&r3), h3);
    }
    __syncthreads();   // all warps done reading swh before spart overwrite
    {
        float2 f0 = __half22float2(h0), f1 = __half22float2(h1);
        float2 f2 = __half22float2(h2a), f3 = __half22float2(h3);
        float4* sp4 = (float4*)&spart[warp * ED + lane * 8];
        sp4[0] = make_float4(f0.x, f0.y, f1.x, f1.y);
        sp4[1] = make_float4(f2.x, f2.y, f3.x, f3.y);
    }
    __syncthreads();
    {
        int ch = tid;
        float r = spart[ch];
#pragma unroll
        for (int p = 1; p < 8; p++) r += spart[p * ED + ch];
        g_feats[(size_t)a * ED + ch] = r;
    }
}

// ---------------------------------------------------------------------------
// launch — inputs bound by unique element counts (order-proof); single stream
// ---------------------------------------------------------------------------
extern "C" void kernel_launch(void* const* d_in, const int* in_sizes, int n_in,
                              void* d_out, int out_size) {
    const float* inst = 0; const float* anchor = 0;
    const float* feat[4] = {0,0,0,0};
    const float* proj = 0; const float* wh = 0;
    const float* Wl = 0; const float* bl = 0;
    const float* Ww = 0; const float* bw = 0;
    const float* Wo = 0; const float* bo = 0;

    for (int i = 0; i < n_in; i++) {
        const float* p = (const float*)d_in[i];
        switch (in_sizes[i]) {
            case 1048576:  inst    = p; break;
            case 45056:    anchor  = p; break;
            case 17301504: feat[0] = p; break;
            case 4325376:  feat[1] = p; break;
            case 1081344:  feat[2] = p; break;
            case 270336:   feat[3] = p; break;
            case 96:       proj    = p; break;
            case 12:       wh      = p; break;
            case 4608:     Wl      = p; break;
            case 18:       bl      = p; break;
            case 638976:   Ww      = p; break;
            case 2496:     bw      = p; break;
            case 65536:    Wo      = p; break;
            case 256:      bo      = p; break;
            default: break;
        }
    }
    float* out = (float*)d_out;

    // 1) fused transpose+fp8 convert (single launch, all 4 levels)
    {
        dim3 grid(468, ED / 32, NC);
        dim3 block(32, 8);
        transpose_all<<<grid, block>>>(feat[0], feat[1], feat[2], feat[3]);
    }

    // 2) per-anchor setup (parallel GEMV)
    setup_kernel<<<NA, 256>>>(inst, anchor, proj, wh, Wl, bl);

    // 3) weight logits GEMM (BM=128, BN=96) -> g_logits
    {
        dim3 grid(NWTS / 96, NA / 128);
        gemm_logits96<<<grid, 256>>>(inst, Ww, bw);
    }

    // 4) fused softmax + compacted aggregation (fp8 features)
    agg_kernel<<<NA, 256>>>();

    // 5) output GEMM: g_feats @ Wo + bo + inst -> d_out
    {
        dim3 grid(ED / 64, NA / 128);
        gemm_bf16_out<<<grid, 256>>>(Wo, bo, inst, out);
    }
}